// round 2
// baseline (speedup 1.0000x reference)
#include <cuda_runtime.h>
#include <math.h>

#define N_NODES 40000
#define E_EDGES 640000
#define F       128
#define HD      128      // H*D
#define NHEADS  4
#define VOCABV  64

// ---------------- scratch (device globals; no allocs allowed) ----------------
__device__ float g_xy   [N_NODES * F];    // x + emb[y]
__device__ float g_q    [N_NODES * HD];
__device__ float g_k    [N_NODES * HD];
__device__ float g_v    [N_NODES * HD];
__device__ float g_acc  [N_NODES * HD];   // skip (x_y@Ws+bs) then += messages
__device__ float g_alpha[E_EDGES * NHEADS]; // logits, then exp(logit-max)
__device__ float g_m    [N_NODES * NHEADS];
__device__ float g_den  [N_NODES * NHEADS];

// ---------------- helpers ----------------
__device__ __forceinline__ void atomicMaxFloat(float* addr, float val) {
    // Standard sign-split trick: int-max for >=0, uint-min for <0.
    if (val >= 0.0f) atomicMax((int*)addr, __float_as_int(val));
    else             atomicMin((unsigned int*)addr, __float_as_uint(val));
}

// ---------------- K0: x_y = x + emb[y] ----------------
__global__ void k_xy(const float* __restrict__ x,
                     const int* __restrict__ y,
                     const float* __restrict__ emb) {
    int i = blockIdx.x * blockDim.x + threadIdx.x;   // float4 index
    if (i >= N_NODES * (F / 4)) return;
    int n  = i >> 5;          // F/4 = 32 float4 per node
    int f4 = i & 31;
    int yv = y[n];
    float4 xv = ((const float4*)x)[i];
    float4 ev = *((const float4*)(emb + yv * F) + f4);
    float4 r  = make_float4(xv.x + ev.x, xv.y + ev.y, xv.z + ev.z, xv.w + ev.w);
    ((float4*)g_xy)[i] = r;
}

// ---------------- K0b: init segment-max / segment-sum ----------------
__global__ void k_init() {
    int i = blockIdx.x * blockDim.x + threadIdx.x;
    if (i < N_NODES * NHEADS) { g_m[i] = -INFINITY; g_den[i] = 0.0f; }
}

// ---------------- K1: fused 4x projection GEMM [N,128]x[128,128] ----------------
// grid: (ceil(N/128), 4). blockIdx.y selects (W, bias, out).
// 256 threads, 128x128 tile, K chunks of 16, 8x8 micro-tile per thread.
__global__ void __launch_bounds__(256, 2)
k_proj(const float* __restrict__ Wq, const float* __restrict__ bq,
       const float* __restrict__ Wk, const float* __restrict__ bk,
       const float* __restrict__ Wv, const float* __restrict__ bv,
       const float* __restrict__ Ws, const float* __restrict__ bs) {
    const float* W; const float* bias; float* out;
    switch (blockIdx.y) {
        case 0:  W = Wq; bias = bq; out = g_q;   break;
        case 1:  W = Wk; bias = bk; out = g_k;   break;
        case 2:  W = Wv; bias = bv; out = g_v;   break;
        default: W = Ws; bias = bs; out = g_acc; break;
    }
    __shared__ float As[16][132];   // [k][m]
    __shared__ float Bs[16][132];   // [k][n]
    int tid = threadIdx.x;
    int m0  = blockIdx.x * 128;
    int ty  = tid >> 4;             // 0..15 -> rows ty*8..+7
    int tx  = tid & 15;             // 0..15 -> cols tx*8..+7

    float acc[8][8];
    #pragma unroll
    for (int i = 0; i < 8; i++)
        #pragma unroll
        for (int j = 0; j < 8; j++) acc[i][j] = 0.0f;

    for (int kc = 0; kc < 128; kc += 16) {
        // stage x tile (transpose to [k][m]); 512 float4, 2 per thread
        #pragma unroll
        for (int it = 0; it < 2; it++) {
            int j   = tid + it * 256;      // 0..511
            int row = j >> 2;              // 0..127
            int k4  = j & 3;
            float4 xv = make_float4(0.f, 0.f, 0.f, 0.f);
            int gr = m0 + row;
            if (gr < N_NODES)
                xv = *(const float4*)(g_xy + gr * 128 + kc + k4 * 4);
            As[k4 * 4 + 0][row] = xv.x;
            As[k4 * 4 + 1][row] = xv.y;
            As[k4 * 4 + 2][row] = xv.z;
            As[k4 * 4 + 3][row] = xv.w;
        }
        // stage W tile [k][n]; fully coalesced
        #pragma unroll
        for (int it = 0; it < 2; it++) {
            int j  = tid + it * 256;       // 0..511
            int kk = j >> 5;               // 0..15
            int n4 = j & 31;
            float4 wv = *(const float4*)(W + (kc + kk) * 128 + n4 * 4);
            *(float4*)(&Bs[kk][n4 * 4]) = wv;
        }
        __syncthreads();
        #pragma unroll
        for (int k = 0; k < 16; k++) {
            float a[8], b[8];
            *(float4*)(a)     = *(const float4*)(&As[k][ty * 8]);
            *(float4*)(a + 4) = *(const float4*)(&As[k][ty * 8 + 4]);
            *(float4*)(b)     = *(const float4*)(&Bs[k][tx * 8]);
            *(float4*)(b + 4) = *(const float4*)(&Bs[k][tx * 8 + 4]);
            #pragma unroll
            for (int i = 0; i < 8; i++)
                #pragma unroll
                for (int j = 0; j < 8; j++)
                    acc[i][j] = fmaf(a[i], b[j], acc[i][j]);
        }
        __syncthreads();
    }
    float bb[8];
    #pragma unroll
    for (int j = 0; j < 8; j++) bb[j] = bias[tx * 8 + j];
    #pragma unroll
    for (int i = 0; i < 8; i++) {
        int gr = m0 + ty * 8 + i;
        if (gr < N_NODES) {
            float4 o0 = make_float4(acc[i][0] + bb[0], acc[i][1] + bb[1],
                                    acc[i][2] + bb[2], acc[i][3] + bb[3]);
            float4 o1 = make_float4(acc[i][4] + bb[4], acc[i][5] + bb[5],
                                    acc[i][6] + bb[6], acc[i][7] + bb[7]);
            *(float4*)(out + gr * 128 + tx * 8)     = o0;
            *(float4*)(out + gr * 128 + tx * 8 + 4) = o1;
        }
    }
}

// ---------------- K2: edge logits + segment max (warp per edge) ----------------
__global__ void k_edge_alpha(const int* __restrict__ ei) {
    int wid  = (blockIdx.x * blockDim.x + threadIdx.x) >> 5;
    int lane = threadIdx.x & 31;
    if (wid >= E_EDGES) return;
    int src = ei[wid];
    int dst = ei[E_EDGES + wid];
    float4 qv = *(const float4*)(g_q + dst * 128 + lane * 4);
    float4 kv = *(const float4*)(g_k + src * 128 + lane * 4);
    float s = qv.x * kv.x + qv.y * kv.y + qv.z * kv.z + qv.w * kv.w;
    // reduce within groups of 8 lanes (one head = 32 dims = 8 lanes * 4)
    s += __shfl_xor_sync(0xffffffffu, s, 1);
    s += __shfl_xor_sync(0xffffffffu, s, 2);
    s += __shfl_xor_sync(0xffffffffu, s, 4);
    if ((lane & 7) == 0) {
        int h = lane >> 3;
        float a = s * 0.17677669529663687f;   // 1/sqrt(32)
        g_alpha[wid * 4 + h] = a;
        atomicMaxFloat(&g_m[dst * 4 + h], a);
    }
}

// ---------------- K3: ea = exp(alpha - m[dst]); denom += ea ----------------
__global__ void k_edge_exp(const int* __restrict__ ei) {
    int id = blockIdx.x * blockDim.x + threadIdx.x;   // over E*4
    if (id >= E_EDGES * NHEADS) return;
    int e = id >> 2;
    int h = id & 3;
    int dst = ei[E_EDGES + e];
    float a  = g_alpha[id];
    float ea = __expf(a - g_m[dst * 4 + h]);
    g_alpha[id] = ea;
    atomicAdd(&g_den[dst * 4 + h], ea);
}

// ---------------- K4: weighted scatter of v[src] into g_acc (warp per edge) ----
__global__ void k_edge_scatter(const int* __restrict__ ei) {
    int wid  = (blockIdx.x * blockDim.x + threadIdx.x) >> 5;
    int lane = threadIdx.x & 31;
    if (wid >= E_EDGES) return;
    int src = ei[wid];
    int dst = ei[E_EDGES + wid];
    int h   = lane >> 3;
    float w = g_alpha[wid * 4 + h] / g_den[dst * 4 + h];  // broadcast within 8 lanes
    float4 vv = *(const float4*)(g_v + src * 128 + lane * 4);
    float* o = g_acc + dst * 128 + lane * 4;
    atomicAdd(o + 0, w * vv.x);
    atomicAdd(o + 1, w * vv.y);
    atomicAdd(o + 2, w * vv.z);
    atomicAdd(o + 3, w * vv.w);
}

// ---------------- K5: classifier [N,128] x [128,64] + bl ----------------
// 128 threads, tile 128x64, 8x8 micro-tile.
__global__ void __launch_bounds__(128, 4)
k_cls(const float* __restrict__ Wl, const float* __restrict__ bl,
      float* __restrict__ out) {
    __shared__ float As[16][132];  // [k][m]
    __shared__ float Bs[16][68];   // [k][n]
    int tid = threadIdx.x;         // 0..127
    int m0  = blockIdx.x * 128;
    int ty  = tid >> 3;            // 0..15
    int tx  = tid & 7;             // 0..7

    float acc[8][8];
    #pragma unroll
    for (int i = 0; i < 8; i++)
        #pragma unroll
        for (int j = 0; j < 8; j++) acc[i][j] = 0.0f;

    for (int kc = 0; kc < 128; kc += 16) {
        #pragma unroll
        for (int it = 0; it < 4; it++) {
            int j   = tid + it * 128;  // 0..511
            int row = j >> 2;
            int k4  = j & 3;
            float4 xv = make_float4(0.f, 0.f, 0.f, 0.f);
            int gr = m0 + row;
            if (gr < N_NODES)
                xv = *(const float4*)(g_acc + gr * 128 + kc + k4 * 4);
            As[k4 * 4 + 0][row] = xv.x;
            As[k4 * 4 + 1][row] = xv.y;
            As[k4 * 4 + 2][row] = xv.z;
            As[k4 * 4 + 3][row] = xv.w;
        }
        #pragma unroll
        for (int it = 0; it < 2; it++) {
            int j  = tid + it * 128;   // 0..255 ; 16 k * 16 f4
            int kk = j >> 4;
            int n4 = j & 15;
            float4 wv = *(const float4*)(Wl + (kc + kk) * 64 + n4 * 4);
            *(float4*)(&Bs[kk][n4 * 4]) = wv;
        }
        __syncthreads();
        #pragma unroll
        for (int k = 0; k < 16; k++) {
            float a[8], b[8];
            *(float4*)(a)     = *(const float4*)(&As[k][ty * 8]);
            *(float4*)(a + 4) = *(const float4*)(&As[k][ty * 8 + 4]);
            *(float4*)(b)     = *(const float4*)(&Bs[k][tx * 8]);
            *(float4*)(b + 4) = *(const float4*)(&Bs[k][tx * 8 + 4]);
            #pragma unroll
            for (int i = 0; i < 8; i++)
                #pragma unroll
                for (int j = 0; j < 8; j++)
                    acc[i][j] = fmaf(a[i], b[j], acc[i][j]);
        }
        __syncthreads();
    }
    float bb[8];
    #pragma unroll
    for (int j = 0; j < 8; j++) bb[j] = bl[tx * 8 + j];
    #pragma unroll
    for (int i = 0; i < 8; i++) {
        int gr = m0 + ty * 8 + i;
        if (gr < N_NODES) {
            float4 o0 = make_float4(acc[i][0] + bb[0], acc[i][1] + bb[1],
                                    acc[i][2] + bb[2], acc[i][3] + bb[3]);
            float4 o1 = make_float4(acc[i][4] + bb[4], acc[i][5] + bb[5],
                                    acc[i][6] + bb[6], acc[i][7] + bb[7]);
            *(float4*)(out + gr * 64 + tx * 8)     = o0;
            *(float4*)(out + gr * 64 + tx * 8 + 4) = o1;
        }
    }
}

// ---------------- launch ----------------
extern "C" void kernel_launch(void* const* d_in, const int* in_sizes, int n_in,
                              void* d_out, int out_size) {
    const float* x   = (const float*)d_in[0];
    const int*   y   = (const int*)d_in[1];     // int64 in ref -> delivered int32
    const int*   ei  = (const int*)d_in[2];     // [2, E] int32
    const float* emb = (const float*)d_in[3];
    const float* Wq = (const float*)d_in[4];  const float* bq = (const float*)d_in[5];
    const float* Wk = (const float*)d_in[6];  const float* bk = (const float*)d_in[7];
    const float* Wv = (const float*)d_in[8];  const float* bv = (const float*)d_in[9];
    const float* Ws = (const float*)d_in[10]; const float* bs = (const float*)d_in[11];
    const float* Wl = (const float*)d_in[12]; const float* bl = (const float*)d_in[13];
    float* out = (float*)d_out;

    k_xy  <<<(N_NODES * (F / 4) + 255) / 256, 256>>>(x, y, emb);
    k_init<<<(N_NODES * NHEADS + 255) / 256, 256>>>();
    k_proj<<<dim3((N_NODES + 127) / 128, 4), 256>>>(Wq, bq, Wk, bk, Wv, bv, Ws, bs);
    k_edge_alpha  <<<E_EDGES / 8, 256>>>(ei);   // 8 warps/block, warp per edge
    k_edge_exp    <<<(E_EDGES * NHEADS + 255) / 256, 256>>>(ei);
    k_edge_scatter<<<E_EDGES / 8, 256>>>(ei);
    k_cls <<<(N_NODES + 127) / 128, 128>>>(Wl, bl, out);
}

// round 3
// speedup vs baseline: 1.4613x; 1.4613x over previous
#include <cuda_runtime.h>
#include <math.h>

#define N_NODES 40000
#define E_EDGES 640000
#define F       128
#define HD      128      // H*D
#define NHEADS  4
#define VOCABV  64

// ---------------- scratch (device globals; no allocs allowed) ----------------
__device__ float g_xy  [N_NODES * F];     // x + emb[y]
__device__ float g_q   [N_NODES * HD];
__device__ float g_k   [N_NODES * HD];
__device__ float g_v   [N_NODES * HD];
__device__ float g_skip[N_NODES * HD];    // x_y@Ws+bs
__device__ float g_msg [N_NODES * HD];    // sum of ea * v[src]  (unnormalized)
__device__ float g_den [N_NODES * NHEADS];

// ---------------- K0: x_y = x + emb[y] ----------------
__global__ void k_xy(const float* __restrict__ x,
                     const int* __restrict__ y,
                     const float* __restrict__ emb) {
    int i = blockIdx.x * blockDim.x + threadIdx.x;   // float4 index
    if (i >= N_NODES * (F / 4)) return;
    int n  = i >> 5;          // 32 float4 per node
    int f4 = i & 31;
    int yv = y[n];
    float4 xv = ((const float4*)x)[i];
    float4 ev = *((const float4*)(emb + yv * F) + f4);
    ((float4*)g_xy)[i] = make_float4(xv.x + ev.x, xv.y + ev.y, xv.z + ev.z, xv.w + ev.w);
}

// ---------------- K0b: zero msg + den ----------------
__global__ void k_zero() {
    int i = blockIdx.x * blockDim.x + threadIdx.x;
    float4 z = make_float4(0.f, 0.f, 0.f, 0.f);
    if (i < N_NODES * HD / 4) ((float4*)g_msg)[i] = z;
    if (i < N_NODES)          ((float4*)g_den)[i] = z;   // N*4 floats == N float4
}

// ---------------- K1: fused 4x projection GEMM [N,128]x[128,128] ----------------
__global__ void __launch_bounds__(256, 2)
k_proj(const float* __restrict__ Wq, const float* __restrict__ bq,
       const float* __restrict__ Wk, const float* __restrict__ bk,
       const float* __restrict__ Wv, const float* __restrict__ bv,
       const float* __restrict__ Ws, const float* __restrict__ bs) {
    const float* W; const float* bias; float* out;
    switch (blockIdx.y) {
        case 0:  W = Wq; bias = bq; out = g_q;    break;
        case 1:  W = Wk; bias = bk; out = g_k;    break;
        case 2:  W = Wv; bias = bv; out = g_v;    break;
        default: W = Ws; bias = bs; out = g_skip; break;
    }
    __shared__ float As[16][132];   // [k][m]
    __shared__ float Bs[16][132];   // [k][n]
    int tid = threadIdx.x;
    int m0  = blockIdx.x * 128;
    int ty  = tid >> 4;
    int tx  = tid & 15;

    float acc[8][8];
    #pragma unroll
    for (int i = 0; i < 8; i++)
        #pragma unroll
        for (int j = 0; j < 8; j++) acc[i][j] = 0.0f;

    for (int kc = 0; kc < 128; kc += 16) {
        #pragma unroll
        for (int it = 0; it < 2; it++) {
            int j   = tid + it * 256;
            int row = j >> 2;
            int k4  = j & 3;
            float4 xv = make_float4(0.f, 0.f, 0.f, 0.f);
            int gr = m0 + row;
            if (gr < N_NODES)
                xv = *(const float4*)(g_xy + gr * 128 + kc + k4 * 4);
            As[k4 * 4 + 0][row] = xv.x;
            As[k4 * 4 + 1][row] = xv.y;
            As[k4 * 4 + 2][row] = xv.z;
            As[k4 * 4 + 3][row] = xv.w;
        }
        #pragma unroll
        for (int it = 0; it < 2; it++) {
            int j  = tid + it * 256;
            int kk = j >> 5;
            int n4 = j & 31;
            float4 wv = *(const float4*)(W + (kc + kk) * 128 + n4 * 4);
            *(float4*)(&Bs[kk][n4 * 4]) = wv;
        }
        __syncthreads();
        #pragma unroll
        for (int k = 0; k < 16; k++) {
            float a[8], b[8];
            *(float4*)(a)     = *(const float4*)(&As[k][ty * 8]);
            *(float4*)(a + 4) = *(const float4*)(&As[k][ty * 8 + 4]);
            *(float4*)(b)     = *(const float4*)(&Bs[k][tx * 8]);
            *(float4*)(b + 4) = *(const float4*)(&Bs[k][tx * 8 + 4]);
            #pragma unroll
            for (int i = 0; i < 8; i++)
                #pragma unroll
                for (int j = 0; j < 8; j++)
                    acc[i][j] = fmaf(a[i], b[j], acc[i][j]);
        }
        __syncthreads();
    }
    float bb[8];
    #pragma unroll
    for (int j = 0; j < 8; j++) bb[j] = bias[tx * 8 + j];
    #pragma unroll
    for (int i = 0; i < 8; i++) {
        int gr = m0 + ty * 8 + i;
        if (gr < N_NODES) {
            float4 o0 = make_float4(acc[i][0] + bb[0], acc[i][1] + bb[1],
                                    acc[i][2] + bb[2], acc[i][3] + bb[3]);
            float4 o1 = make_float4(acc[i][4] + bb[4], acc[i][5] + bb[5],
                                    acc[i][6] + bb[6], acc[i][7] + bb[7]);
            *(float4*)(out + gr * 128 + tx * 8)     = o0;
            *(float4*)(out + gr * 128 + tx * 8 + 4) = o1;
        }
    }
}

// ---------------- K2: single fused edge pass ----------------
// warp per edge: alpha = (q[dst].k[src])/sqrt(D) per head; ea = exp(alpha);
// den[dst][h] += ea; msg[dst] += ea * v[src]. No segment-max: mathematically
// identical after normalization (logits are O(5), safely inside fp32 exp range).
__global__ void __launch_bounds__(256)
k_edge(const int* __restrict__ ei) {
    int wid  = (blockIdx.x * blockDim.x + threadIdx.x) >> 5;
    int lane = threadIdx.x & 31;
    if (wid >= E_EDGES) return;
    int src = ei[wid];
    int dst = ei[E_EDGES + wid];

    float4 qv = *(const float4*)(g_q + dst * 128 + lane * 4);
    float4 kv = *(const float4*)(g_k + src * 128 + lane * 4);
    float s = qv.x * kv.x + qv.y * kv.y + qv.z * kv.z + qv.w * kv.w;
    // butterfly within each 8-lane group (one head = 32 dims)
    s += __shfl_xor_sync(0xffffffffu, s, 1);
    s += __shfl_xor_sync(0xffffffffu, s, 2);
    s += __shfl_xor_sync(0xffffffffu, s, 4);
    float ea = __expf(s * 0.17677669529663687f);   // 1/sqrt(32)

    if ((lane & 7) == 0)
        atomicAdd(&g_den[dst * 4 + (lane >> 3)], ea);

    float4 vv = *(const float4*)(g_v + src * 128 + lane * 4);
    float* o = g_msg + dst * 128 + lane * 4;
    asm volatile("red.global.add.v4.f32 [%0], {%1, %2, %3, %4};"
                 :: "l"(o), "f"(ea * vv.x), "f"(ea * vv.y),
                    "f"(ea * vv.z), "f"(ea * vv.w)
                 : "memory");
}

// ---------------- K3: classifier with fused normalize + skip ----------------
// A[n][f] = msg[n][f]/den[n][f>>5] (0 if den==0) + skip[n][f]; out = A @ Wl + bl
__global__ void __launch_bounds__(128, 4)
k_cls(const float* __restrict__ Wl, const float* __restrict__ bl,
      float* __restrict__ out) {
    __shared__ float As[16][132];  // [k][m]
    __shared__ float Bs[16][68];   // [k][n]
    int tid = threadIdx.x;
    int m0  = blockIdx.x * 128;
    int ty  = tid >> 3;
    int tx  = tid & 7;

    float acc[8][8];
    #pragma unroll
    for (int i = 0; i < 8; i++)
        #pragma unroll
        for (int j = 0; j < 8; j++) acc[i][j] = 0.0f;

    for (int kc = 0; kc < 128; kc += 16) {
        #pragma unroll
        for (int it = 0; it < 4; it++) {
            int j   = tid + it * 128;
            int row = j >> 2;
            int k4  = j & 3;
            int gr  = m0 + row;
            float4 av = make_float4(0.f, 0.f, 0.f, 0.f);
            if (gr < N_NODES) {
                int f0 = kc + k4 * 4;              // all 4 dims in same head
                float4 mv = *(const float4*)(g_msg  + gr * 128 + f0);
                float4 sv = *(const float4*)(g_skip + gr * 128 + f0);
                float  d  = g_den[gr * 4 + (f0 >> 5)];
                float  inv = (d > 0.f) ? (1.0f / d) : 0.f;
                av = make_float4(fmaf(mv.x, inv, sv.x), fmaf(mv.y, inv, sv.y),
                                 fmaf(mv.z, inv, sv.z), fmaf(mv.w, inv, sv.w));
            }
            As[k4 * 4 + 0][row] = av.x;
            As[k4 * 4 + 1][row] = av.y;
            As[k4 * 4 + 2][row] = av.z;
            As[k4 * 4 + 3][row] = av.w;
        }
        #pragma unroll
        for (int it = 0; it < 2; it++) {
            int j  = tid + it * 128;
            int kk = j >> 4;
            int n4 = j & 15;
            float4 wv = *(const float4*)(Wl + (kc + kk) * 64 + n4 * 4);
            *(float4*)(&Bs[kk][n4 * 4]) = wv;
        }
        __syncthreads();
        #pragma unroll
        for (int k = 0; k < 16; k++) {
            float a[8], b[8];
            *(float4*)(a)     = *(const float4*)(&As[k][ty * 8]);
            *(float4*)(a + 4) = *(const float4*)(&As[k][ty * 8 + 4]);
            *(float4*)(b)     = *(const float4*)(&Bs[k][tx * 8]);
            *(float4*)(b + 4) = *(const float4*)(&Bs[k][tx * 8 + 4]);
            #pragma unroll
            for (int i = 0; i < 8; i++)
                #pragma unroll
                for (int j = 0; j < 8; j++)
                    acc[i][j] = fmaf(a[i], b[j], acc[i][j]);
        }
        __syncthreads();
    }
    float bb[8];
    #pragma unroll
    for (int j = 0; j < 8; j++) bb[j] = bl[tx * 8 + j];
    #pragma unroll
    for (int i = 0; i < 8; i++) {
        int gr = m0 + ty * 8 + i;
        if (gr < N_NODES) {
            float4 o0 = make_float4(acc[i][0] + bb[0], acc[i][1] + bb[1],
                                    acc[i][2] + bb[2], acc[i][3] + bb[3]);
            float4 o1 = make_float4(acc[i][4] + bb[4], acc[i][5] + bb[5],
                                    acc[i][6] + bb[6], acc[i][7] + bb[7]);
            *(float4*)(out + gr * 64 + tx * 8)     = o0;
            *(float4*)(out + gr * 64 + tx * 8 + 4) = o1;
        }
    }
}

// ---------------- launch ----------------
extern "C" void kernel_launch(void* const* d_in, const int* in_sizes, int n_in,
                              void* d_out, int out_size) {
    const float* x   = (const float*)d_in[0];
    const int*   y   = (const int*)d_in[1];     // int64 in ref -> delivered int32
    const int*   ei  = (const int*)d_in[2];     // [2, E] int32
    const float* emb = (const float*)d_in[3];
    const float* Wq = (const float*)d_in[4];  const float* bq = (const float*)d_in[5];
    const float* Wk = (const float*)d_in[6];  const float* bk = (const float*)d_in[7];
    const float* Wv = (const float*)d_in[8];  const float* bv = (const float*)d_in[9];
    const float* Ws = (const float*)d_in[10]; const float* bs = (const float*)d_in[11];
    const float* Wl = (const float*)d_in[12]; const float* bl = (const float*)d_in[13];
    float* out = (float*)d_out;

    k_xy  <<<(N_NODES * (F / 4) + 255) / 256, 256>>>(x, y, emb);
    k_zero<<<(N_NODES * HD / 4 + 255) / 256, 256>>>();
    k_proj<<<dim3((N_NODES + 127) / 128, 4), 256>>>(Wq, bq, Wk, bk, Wv, bv, Ws, bs);
    k_edge<<<E_EDGES / 8, 256>>>(ei);           // warp per edge
    k_cls <<<(N_NODES + 127) / 128, 128>>>(Wl, bl, out);
}

// round 4
// speedup vs baseline: 1.6634x; 1.1383x over previous
#include <cuda_runtime.h>
#include <math.h>

#define N_NODES 40000
#define E_EDGES 640000
#define F       128
#define HD      128      // H*D
#define NHEADS  4
#define VOCABV  64

// packed fp32x2 helpers (sm_100a+)
#define FMA2(d, a, b, c) \
    asm("fma.rn.f32x2 %0, %1, %2, %3;" : "=l"(d) : "l"(a), "l"(b), "l"(c))
#define PACK_DUP(d, f) \
    asm("mov.b64 %0, {%1, %1};" : "=l"(d) : "f"(f))
#define UNPACK2(lo, hi, d) \
    asm("mov.b64 {%0, %1}, %2;" : "=f"(lo), "=f"(hi) : "l"(d))

// ---------------- scratch (device globals; no allocs allowed) ----------------
__device__ float g_xy  [N_NODES * F];     // x + emb[y]
__device__ float g_q   [N_NODES * HD];
__device__ float g_k   [N_NODES * HD];
__device__ float g_v   [N_NODES * HD];
__device__ float g_skip[N_NODES * HD];    // x_y@Ws+bs
__device__ float g_msg [N_NODES * HD];    // sum of ea * v[src]  (unnormalized)
__device__ float g_den [N_NODES * NHEADS];

// ---------------- K0: x_y = x + emb[y] ----------------
__global__ void k_xy(const float* __restrict__ x,
                     const int* __restrict__ y,
                     const float* __restrict__ emb) {
    int i = blockIdx.x * blockDim.x + threadIdx.x;   // float4 index
    if (i >= N_NODES * (F / 4)) return;
    int n  = i >> 5;
    int f4 = i & 31;
    int yv = y[n];
    float4 xv = ((const float4*)x)[i];
    float4 ev = *((const float4*)(emb + yv * F) + f4);
    ((float4*)g_xy)[i] = make_float4(xv.x + ev.x, xv.y + ev.y, xv.z + ev.z, xv.w + ev.w);
}

// ---------------- K0b: zero msg + den ----------------
__global__ void k_zero() {
    int i = blockIdx.x * blockDim.x + threadIdx.x;
    float4 z = make_float4(0.f, 0.f, 0.f, 0.f);
    if (i < N_NODES * HD / 4) ((float4*)g_msg)[i] = z;
    if (i < N_NODES)          ((float4*)g_den)[i] = z;
}

// ---------------- K1: fused 4x projection GEMM, f32x2 inner loop ----------------
__global__ void __launch_bounds__(256, 2)
k_proj(const float* __restrict__ Wq, const float* __restrict__ bq,
       const float* __restrict__ Wk, const float* __restrict__ bk,
       const float* __restrict__ Wv, const float* __restrict__ bv,
       const float* __restrict__ Ws, const float* __restrict__ bs) {
    const float* W; const float* bias; float* out;
    switch (blockIdx.y) {
        case 0:  W = Wq; bias = bq; out = g_q;    break;
        case 1:  W = Wk; bias = bk; out = g_k;    break;
        case 2:  W = Wv; bias = bv; out = g_v;    break;
        default: W = Ws; bias = bs; out = g_skip; break;
    }
    __shared__ float As[16][132];   // [k][m]
    __shared__ float Bs[16][132];   // [k][n]
    int tid = threadIdx.x;
    int m0  = blockIdx.x * 128;
    int ty  = tid >> 4;
    int tx  = tid & 15;

    unsigned long long acc2[8][4];  // packed f32x2 pairs along n
    #pragma unroll
    for (int i = 0; i < 8; i++)
        #pragma unroll
        for (int j = 0; j < 4; j++) acc2[i][j] = 0ULL;

    for (int kc = 0; kc < 128; kc += 16) {
        #pragma unroll
        for (int it = 0; it < 2; it++) {
            int j   = tid + it * 256;
            int row = j >> 2;
            int k4  = j & 3;
            float4 xv = make_float4(0.f, 0.f, 0.f, 0.f);
            int gr = m0 + row;
            if (gr < N_NODES)
                xv = *(const float4*)(g_xy + gr * 128 + kc + k4 * 4);
            As[k4 * 4 + 0][row] = xv.x;
            As[k4 * 4 + 1][row] = xv.y;
            As[k4 * 4 + 2][row] = xv.z;
            As[k4 * 4 + 3][row] = xv.w;
        }
        #pragma unroll
        for (int it = 0; it < 2; it++) {
            int j  = tid + it * 256;
            int kk = j >> 5;
            int n4 = j & 31;
            float4 wv = *(const float4*)(W + (kc + kk) * 128 + n4 * 4);
            *(float4*)(&Bs[kk][n4 * 4]) = wv;
        }
        __syncthreads();
        #pragma unroll
        for (int k = 0; k < 16; k++) {
            float a[8];
            *(float4*)(a)     = *(const float4*)(&As[k][ty * 8]);
            *(float4*)(a + 4) = *(const float4*)(&As[k][ty * 8 + 4]);
            unsigned long long b2[4];
            #pragma unroll
            for (int j = 0; j < 4; j++)
                b2[j] = *(const unsigned long long*)(&Bs[k][tx * 8 + j * 2]);
            #pragma unroll
            for (int i = 0; i < 8; i++) {
                unsigned long long av;
                PACK_DUP(av, a[i]);
                #pragma unroll
                for (int j = 0; j < 4; j++)
                    FMA2(acc2[i][j], av, b2[j], acc2[i][j]);
            }
        }
        __syncthreads();
    }
    float bb[8];
    #pragma unroll
    for (int j = 0; j < 8; j++) bb[j] = bias[tx * 8 + j];
    #pragma unroll
    for (int i = 0; i < 8; i++) {
        int gr = m0 + ty * 8 + i;
        if (gr < N_NODES) {
            float o[8];
            #pragma unroll
            for (int j = 0; j < 4; j++)
                UNPACK2(o[2 * j], o[2 * j + 1], acc2[i][j]);
            float4 o0 = make_float4(o[0] + bb[0], o[1] + bb[1], o[2] + bb[2], o[3] + bb[3]);
            float4 o1 = make_float4(o[4] + bb[4], o[5] + bb[5], o[6] + bb[6], o[7] + bb[7]);
            *(float4*)(out + gr * 128 + tx * 8)     = o0;
            *(float4*)(out + gr * 128 + tx * 8 + 4) = o1;
        }
    }
}

// ---------------- K2: fused edge pass, 2 edges per warp (MLP=6) ----------------
__global__ void __launch_bounds__(256)
k_edge(const int* __restrict__ ei) {
    int w    = (blockIdx.x * blockDim.x + threadIdx.x) >> 5;  // 0 .. E/2-1
    int lane = threadIdx.x & 31;
    int e0 = w * 2;
    if (e0 >= E_EDGES) return;
    int e1 = e0 + 1;
    int src0 = ei[e0], dst0 = ei[E_EDGES + e0];
    int src1 = ei[e1], dst1 = ei[E_EDGES + e1];

    // front-issue all six gathers
    float4 q0 = *(const float4*)(g_q + dst0 * 128 + lane * 4);
    float4 k0 = *(const float4*)(g_k + src0 * 128 + lane * 4);
    float4 q1 = *(const float4*)(g_q + dst1 * 128 + lane * 4);
    float4 k1 = *(const float4*)(g_k + src1 * 128 + lane * 4);
    float4 v0 = *(const float4*)(g_v + src0 * 128 + lane * 4);
    float4 v1 = *(const float4*)(g_v + src1 * 128 + lane * 4);

    float s0 = q0.x * k0.x + q0.y * k0.y + q0.z * k0.z + q0.w * k0.w;
    float s1 = q1.x * k1.x + q1.y * k1.y + q1.z * k1.z + q1.w * k1.w;
    // butterfly within each 8-lane group (one head = 32 dims)
    s0 += __shfl_xor_sync(0xffffffffu, s0, 1);
    s1 += __shfl_xor_sync(0xffffffffu, s1, 1);
    s0 += __shfl_xor_sync(0xffffffffu, s0, 2);
    s1 += __shfl_xor_sync(0xffffffffu, s1, 2);
    s0 += __shfl_xor_sync(0xffffffffu, s0, 4);
    s1 += __shfl_xor_sync(0xffffffffu, s1, 4);
    float ea0 = __expf(s0 * 0.17677669529663687f);   // 1/sqrt(32)
    float ea1 = __expf(s1 * 0.17677669529663687f);

    if ((lane & 7) == 0) {
        int h = lane >> 3;
        atomicAdd(&g_den[dst0 * 4 + h], ea0);
        atomicAdd(&g_den[dst1 * 4 + h], ea1);
    }

    float* o0 = g_msg + dst0 * 128 + lane * 4;
    asm volatile("red.global.add.v4.f32 [%0], {%1, %2, %3, %4};"
                 :: "l"(o0), "f"(ea0 * v0.x), "f"(ea0 * v0.y),
                    "f"(ea0 * v0.z), "f"(ea0 * v0.w) : "memory");
    float* o1 = g_msg + dst1 * 128 + lane * 4;
    asm volatile("red.global.add.v4.f32 [%0], {%1, %2, %3, %4};"
                 :: "l"(o1), "f"(ea1 * v1.x), "f"(ea1 * v1.y),
                    "f"(ea1 * v1.z), "f"(ea1 * v1.w) : "memory");
}

// ---------------- K3: classifier, fused normalize + skip, f32x2 -----------------
__global__ void __launch_bounds__(128, 4)
k_cls(const float* __restrict__ Wl, const float* __restrict__ bl,
      float* __restrict__ out) {
    __shared__ float As[16][132];  // [k][m]
    __shared__ float Bs[16][68];   // [k][n]
    int tid = threadIdx.x;
    int m0  = blockIdx.x * 128;
    int ty  = tid >> 3;
    int tx  = tid & 7;

    unsigned long long acc2[8][4];
    #pragma unroll
    for (int i = 0; i < 8; i++)
        #pragma unroll
        for (int j = 0; j < 4; j++) acc2[i][j] = 0ULL;

    for (int kc = 0; kc < 128; kc += 16) {
        #pragma unroll
        for (int it = 0; it < 4; it++) {
            int j   = tid + it * 128;
            int row = j >> 2;
            int k4  = j & 3;
            int gr  = m0 + row;
            float4 av = make_float4(0.f, 0.f, 0.f, 0.f);
            if (gr < N_NODES) {
                int f0 = kc + k4 * 4;              // all 4 dims in same head
                float4 mv = *(const float4*)(g_msg  + gr * 128 + f0);
                float4 sv = *(const float4*)(g_skip + gr * 128 + f0);
                float  d  = g_den[gr * 4 + (f0 >> 5)];
                float  inv = (d > 0.f) ? (1.0f / d) : 0.f;
                av = make_float4(fmaf(mv.x, inv, sv.x), fmaf(mv.y, inv, sv.y),
                                 fmaf(mv.z, inv, sv.z), fmaf(mv.w, inv, sv.w));
            }
            As[k4 * 4 + 0][row] = av.x;
            As[k4 * 4 + 1][row] = av.y;
            As[k4 * 4 + 2][row] = av.z;
            As[k4 * 4 + 3][row] = av.w;
        }
        #pragma unroll
        for (int it = 0; it < 2; it++) {
            int j  = tid + it * 128;
            int kk = j >> 4;
            int n4 = j & 15;
            float4 wv = *(const float4*)(Wl + (kc + kk) * 64 + n4 * 4);
            *(float4*)(&Bs[kk][n4 * 4]) = wv;
        }
        __syncthreads();
        #pragma unroll
        for (int k = 0; k < 16; k++) {
            float a[8];
            *(float4*)(a)     = *(const float4*)(&As[k][ty * 8]);
            *(float4*)(a + 4) = *(const float4*)(&As[k][ty * 8 + 4]);
            unsigned long long b2[4];
            #pragma unroll
            for (int j = 0; j < 4; j++)
                b2[j] = *(const unsigned long long*)(&Bs[k][tx * 8 + j * 2]);
            #pragma unroll
            for (int i = 0; i < 8; i++) {
                unsigned long long av;
                PACK_DUP(av, a[i]);
                #pragma unroll
                for (int j = 0; j < 4; j++)
                    FMA2(acc2[i][j], av, b2[j], acc2[i][j]);
            }
        }
        __syncthreads();
    }
    float bb[8];
    #pragma unroll
    for (int j = 0; j < 8; j++) bb[j] = bl[tx * 8 + j];
    #pragma unroll
    for (int i = 0; i < 8; i++) {
        int gr = m0 + ty * 8 + i;
        if (gr < N_NODES) {
            float o[8];
            #pragma unroll
            for (int j = 0; j < 4; j++)
                UNPACK2(o[2 * j], o[2 * j + 1], acc2[i][j]);
            float4 o0 = make_float4(o[0] + bb[0], o[1] + bb[1], o[2] + bb[2], o[3] + bb[3]);
            float4 o1 = make_float4(o[4] + bb[4], o[5] + bb[5], o[6] + bb[6], o[7] + bb[7]);
            *(float4*)(out + gr * 64 + tx * 8)     = o0;
            *(float4*)(out + gr * 64 + tx * 8 + 4) = o1;
        }
    }
}

// ---------------- launch ----------------
extern "C" void kernel_launch(void* const* d_in, const int* in_sizes, int n_in,
                              void* d_out, int out_size) {
    const float* x   = (const float*)d_in[0];
    const int*   y   = (const int*)d_in[1];
    const int*   ei  = (const int*)d_in[2];
    const float* emb = (const float*)d_in[3];
    const float* Wq = (const float*)d_in[4];  const float* bq = (const float*)d_in[5];
    const float* Wk = (const float*)d_in[6];  const float* bk = (const float*)d_in[7];
    const float* Wv = (const float*)d_in[8];  const float* bv = (const float*)d_in[9];
    const float* Ws = (const float*)d_in[10]; const float* bs = (const float*)d_in[11];
    const float* Wl = (const float*)d_in[12]; const float* bl = (const float*)d_in[13];
    float* out = (float*)d_out;

    k_xy  <<<(N_NODES * (F / 4) + 255) / 256, 256>>>(x, y, emb);
    k_zero<<<(N_NODES * HD / 4 + 255) / 256, 256>>>();
    k_proj<<<dim3((N_NODES + 127) / 128, 4), 256>>>(Wq, bq, Wk, bk, Wv, bv, Ws, bs);
    k_edge<<<(E_EDGES / 2 + 7) / 8, 256>>>(ei);   // 2 edges per warp, 8 warps/block
    k_cls <<<(N_NODES + 127) / 128, 128>>>(Wl, bl, out);
}

// round 5
// speedup vs baseline: 1.9837x; 1.1926x over previous
#include <cuda_runtime.h>
#include <cuda_bf16.h>
#include <math.h>

#define N_NODES 40000
#define E_EDGES 640000
#define F       128
#define HD      128
#define NHEADS  4
#define VOCABV  64

// packed fp32x2 helpers (sm_100a+)
#define FMA2(d, a, b, c) \
    asm("fma.rn.f32x2 %0, %1, %2, %3;" : "=l"(d) : "l"(a), "l"(b), "l"(c))
#define PACK_DUP(d, f) \
    asm("mov.b64 %0, {%1, %1};" : "=l"(d) : "f"(f))
#define UNPACK2(lo, hi, d) \
    asm("mov.b64 {%0, %1}, %2;" : "=f"(lo), "=f"(hi) : "l"(d))

// ---------------- scratch ----------------
__device__ unsigned g_xh [N_NODES * F / 2];   // bf16 hi pairs of x_y
__device__ unsigned g_xl [N_NODES * F / 2];   // bf16 lo pairs
__device__ float g_q   [N_NODES * HD];
__device__ float g_k   [N_NODES * HD];
__device__ float g_v   [N_NODES * HD];
__device__ float g_skip[N_NODES * HD];
__device__ float g_msg [N_NODES * HD];
__device__ float g_den [N_NODES * NHEADS];

__device__ __forceinline__ unsigned pack_bf16(float lo, float hi) {
    unsigned r;
    asm("cvt.rn.bf16x2.f32 %0, %1, %2;" : "=r"(r) : "f"(hi), "f"(lo));
    return r;
}

__device__ __forceinline__ void mma_bf16(float* d, const unsigned* a, const unsigned* b) {
    asm("mma.sync.aligned.m16n8k16.row.col.f32.bf16.bf16.f32 "
        "{%0,%1,%2,%3}, {%4,%5,%6,%7}, {%8,%9}, {%0,%1,%2,%3};"
        : "+f"(d[0]), "+f"(d[1]), "+f"(d[2]), "+f"(d[3])
        : "r"(a[0]), "r"(a[1]), "r"(a[2]), "r"(a[3]), "r"(b[0]), "r"(b[1]));
}

// ---------------- K0: x_y = x + emb[y], split to bf16 hi/lo ----------------
__global__ void k_xy(const float* __restrict__ x,
                     const int* __restrict__ y,
                     const float* __restrict__ emb) {
    int i = blockIdx.x * blockDim.x + threadIdx.x;   // float4 index over N*32
    if (i >= N_NODES * (F / 4)) return;
    int n  = i >> 5;
    int f4 = i & 31;
    int yv = y[n];
    float4 xv = ((const float4*)x)[i];
    float4 ev = *((const float4*)(emb + yv * F) + f4);
    float r[4] = { xv.x + ev.x, xv.y + ev.y, xv.z + ev.z, xv.w + ev.w };
    unsigned h[2], l[2];
    #pragma unroll
    for (int p = 0; p < 2; p++) {
        float a = r[2 * p], b = r[2 * p + 1];
        float ha = __bfloat162float(__float2bfloat16_rn(a));
        float hb = __bfloat162float(__float2bfloat16_rn(b));
        h[p] = pack_bf16(ha, hb);
        l[p] = pack_bf16(a - ha, b - hb);
    }
    ((uint2*)g_xh)[i] = make_uint2(h[0], h[1]);
    ((uint2*)g_xl)[i] = make_uint2(l[0], l[1]);
}

// ---------------- K0b: zero msg + den ----------------
__global__ void k_zero() {
    int i = blockIdx.x * blockDim.x + threadIdx.x;
    float4 z = make_float4(0.f, 0.f, 0.f, 0.f);
    if (i < N_NODES * HD / 4) ((float4*)g_msg)[i] = z;
    if (i < N_NODES)          ((float4*)g_den)[i] = z;
}

// ---------------- K1: tensor-core projection GEMM (bf16 3-term split) --------
// grid (313, 4); 256 threads = 8 warps as 4(m) x 2(n); warp tile 32m x 64n.
// K chunks of 16. A/B staged in smem as bf16x2-packed [row][kpair] stride 9.
__global__ void __launch_bounds__(256, 2)
k_proj(const float* __restrict__ Wq, const float* __restrict__ bq,
       const float* __restrict__ Wk, const float* __restrict__ bk,
       const float* __restrict__ Wv, const float* __restrict__ bv,
       const float* __restrict__ Ws, const float* __restrict__ bs) {
    const float* W; const float* bias; float* out;
    switch (blockIdx.y) {
        case 0:  W = Wq; bias = bq; out = g_q;    break;
        case 1:  W = Wk; bias = bk; out = g_k;    break;
        case 2:  W = Wv; bias = bv; out = g_v;    break;
        default: W = Ws; bias = bs; out = g_skip; break;
    }
    __shared__ unsigned Ah[128 * 9], Al[128 * 9], Bh[128 * 9], Bl[128 * 9];

    int tid  = threadIdx.x;
    int wid  = tid >> 5, lane = tid & 31;
    int wm   = wid >> 1;            // 0..3 : rows wm*32 .. +32
    int wn   = wid & 1;             // 0..1 : cols wn*64 .. +64
    int g    = lane >> 2;           // 0..7
    int tig  = lane & 3;            // 0..3
    int m0   = blockIdx.x * 128;

    float C[2][8][4];
    #pragma unroll
    for (int mt = 0; mt < 2; mt++)
        #pragma unroll
        for (int nt = 0; nt < 8; nt++)
            #pragma unroll
            for (int c = 0; c < 4; c++) C[mt][nt][c] = 0.f;

    for (int kc = 0; kc < 128; kc += 16) {
        // stage A: 128 rows x 8 kpairs, from precomputed bf16 pairs
        #pragma unroll
        for (int t = 0; t < 4; t++) {
            int idx = tid + t * 256;        // 0..1023
            int row = idx >> 3, kp = idx & 7;
            int gr  = m0 + row;
            unsigned vh = 0u, vl = 0u;
            if (gr < N_NODES) {
                int src = gr * 64 + (kc >> 1) + kp;
                vh = g_xh[src];
                vl = g_xl[src];
            }
            Ah[row * 9 + kp] = vh;
            Al[row * 9 + kp] = vl;
        }
        // stage B: split W on the fly; entry (n, kp)
        #pragma unroll
        for (int t = 0; t < 4; t++) {
            int idx = tid + t * 256;
            int n  = idx & 127, kp = idx >> 7;  // kp 0..7
            float w0 = W[(kc + 2 * kp)     * 128 + n];
            float w1 = W[(kc + 2 * kp + 1) * 128 + n];
            float h0 = __bfloat162float(__float2bfloat16_rn(w0));
            float h1 = __bfloat162float(__float2bfloat16_rn(w1));
            Bh[n * 9 + kp] = pack_bf16(h0, h1);
            Bl[n * 9 + kp] = pack_bf16(w0 - h0, w1 - h1);
        }
        __syncthreads();

        unsigned ah[2][4], al[2][4];
        #pragma unroll
        for (int mt = 0; mt < 2; mt++) {
            int base = wm * 32 + mt * 16;
            ah[mt][0] = Ah[(base + g)     * 9 + tig];
            ah[mt][1] = Ah[(base + g + 8) * 9 + tig];
            ah[mt][2] = Ah[(base + g)     * 9 + tig + 4];
            ah[mt][3] = Ah[(base + g + 8) * 9 + tig + 4];
            al[mt][0] = Al[(base + g)     * 9 + tig];
            al[mt][1] = Al[(base + g + 8) * 9 + tig];
            al[mt][2] = Al[(base + g)     * 9 + tig + 4];
            al[mt][3] = Al[(base + g + 8) * 9 + tig + 4];
        }
        #pragma unroll
        for (int nt = 0; nt < 8; nt++) {
            int nb = wn * 64 + nt * 8;
            unsigned bh[2] = { Bh[(nb + g) * 9 + tig], Bh[(nb + g) * 9 + tig + 4] };
            unsigned bl[2] = { Bl[(nb + g) * 9 + tig], Bl[(nb + g) * 9 + tig + 4] };
            #pragma unroll
            for (int mt = 0; mt < 2; mt++) {
                mma_bf16(C[mt][nt], ah[mt], bh);   // hi*hi
                mma_bf16(C[mt][nt], ah[mt], bl);   // hi*lo
                mma_bf16(C[mt][nt], al[mt], bh);   // lo*hi
            }
        }
        __syncthreads();
    }

    // epilogue: c0=(g,2tig) c1=(g,2tig+1) c2=(g+8,2tig) c3=(g+8,2tig+1)
    #pragma unroll
    for (int nt = 0; nt < 8; nt++) {
        int col = wn * 64 + nt * 8 + 2 * tig;
        float2 b2 = *(const float2*)(bias + col);
        #pragma unroll
        for (int mt = 0; mt < 2; mt++) {
            int r0 = m0 + wm * 32 + mt * 16 + g;
            int r1 = r0 + 8;
            if (r0 < N_NODES)
                *(float2*)(out + r0 * 128 + col) =
                    make_float2(C[mt][nt][0] + b2.x, C[mt][nt][1] + b2.y);
            if (r1 < N_NODES)
                *(float2*)(out + r1 * 128 + col) =
                    make_float2(C[mt][nt][2] + b2.x, C[mt][nt][3] + b2.y);
        }
    }
}

// ---------------- K2: fused edge pass, 4 edges per warp (MLP=12) ----------------
__global__ void __launch_bounds__(256)
k_edge(const int* __restrict__ ei) {
    int w    = (blockIdx.x * blockDim.x + threadIdx.x) >> 5;
    int lane = threadIdx.x & 31;
    int e0 = w * 4;
    if (e0 >= E_EDGES) return;
    int src[4], dst[4];
    #pragma unroll
    for (int j = 0; j < 4; j++) {
        src[j] = ei[e0 + j];
        dst[j] = ei[E_EDGES + e0 + j];
    }
    float4 qv[4], kv[4], vv[4];
    #pragma unroll
    for (int j = 0; j < 4; j++) qv[j] = *(const float4*)(g_q + dst[j] * 128 + lane * 4);
    #pragma unroll
    for (int j = 0; j < 4; j++) kv[j] = *(const float4*)(g_k + src[j] * 128 + lane * 4);
    #pragma unroll
    for (int j = 0; j < 4; j++) vv[j] = *(const float4*)(g_v + src[j] * 128 + lane * 4);

    float s[4], ea[4];
    #pragma unroll
    for (int j = 0; j < 4; j++)
        s[j] = qv[j].x * kv[j].x + qv[j].y * kv[j].y + qv[j].z * kv[j].z + qv[j].w * kv[j].w;
    #pragma unroll
    for (int j = 0; j < 4; j++) s[j] += __shfl_xor_sync(0xffffffffu, s[j], 1);
    #pragma unroll
    for (int j = 0; j < 4; j++) s[j] += __shfl_xor_sync(0xffffffffu, s[j], 2);
    #pragma unroll
    for (int j = 0; j < 4; j++) s[j] += __shfl_xor_sync(0xffffffffu, s[j], 4);
    #pragma unroll
    for (int j = 0; j < 4; j++) ea[j] = __expf(s[j] * 0.17677669529663687f);

    if ((lane & 7) == 0) {
        int h = lane >> 3;
        #pragma unroll
        for (int j = 0; j < 4; j++) atomicAdd(&g_den[dst[j] * 4 + h], ea[j]);
    }
    #pragma unroll
    for (int j = 0; j < 4; j++) {
        float* o = g_msg + dst[j] * 128 + lane * 4;
        asm volatile("red.global.add.v4.f32 [%0], {%1, %2, %3, %4};"
                     :: "l"(o), "f"(ea[j] * vv[j].x), "f"(ea[j] * vv[j].y),
                        "f"(ea[j] * vv[j].z), "f"(ea[j] * vv[j].w) : "memory");
    }
}

// ---------------- K3: classifier, fused normalize + skip, f32x2 -----------------
__global__ void __launch_bounds__(128, 4)
k_cls(const float* __restrict__ Wl, const float* __restrict__ bl,
      float* __restrict__ out) {
    __shared__ float As[16][132];
    __shared__ float Bs[16][68];
    int tid = threadIdx.x;
    int m0  = blockIdx.x * 128;
    int ty  = tid >> 3;
    int tx  = tid & 7;

    unsigned long long acc2[8][4];
    #pragma unroll
    for (int i = 0; i < 8; i++)
        #pragma unroll
        for (int j = 0; j < 4; j++) acc2[i][j] = 0ULL;

    for (int kc = 0; kc < 128; kc += 16) {
        #pragma unroll
        for (int it = 0; it < 4; it++) {
            int j   = tid + it * 128;
            int row = j >> 2;
            int k4  = j & 3;
            int gr  = m0 + row;
            float4 av = make_float4(0.f, 0.f, 0.f, 0.f);
            if (gr < N_NODES) {
                int f0 = kc + k4 * 4;
                float4 mv = *(const float4*)(g_msg  + gr * 128 + f0);
                float4 sv = *(const float4*)(g_skip + gr * 128 + f0);
                float  d  = g_den[gr * 4 + (f0 >> 5)];
                float  inv = (d > 0.f) ? (1.0f / d) : 0.f;
                av = make_float4(fmaf(mv.x, inv, sv.x), fmaf(mv.y, inv, sv.y),
                                 fmaf(mv.z, inv, sv.z), fmaf(mv.w, inv, sv.w));
            }
            As[k4 * 4 + 0][row] = av.x;
            As[k4 * 4 + 1][row] = av.y;
            As[k4 * 4 + 2][row] = av.z;
            As[k4 * 4 + 3][row] = av.w;
        }
        #pragma unroll
        for (int it = 0; it < 2; it++) {
            int j  = tid + it * 128;
            int kk = j >> 4;
            int n4 = j & 15;
            float4 wv = *(const float4*)(Wl + (kc + kk) * 64 + n4 * 4);
            *(float4*)(&Bs[kk][n4 * 4]) = wv;
        }
        __syncthreads();
        #pragma unroll
        for (int k = 0; k < 16; k++) {
            float a[8];
            *(float4*)(a)     = *(const float4*)(&As[k][ty * 8]);
            *(float4*)(a + 4) = *(const float4*)(&As[k][ty * 8 + 4]);
            unsigned long long b2[4];
            #pragma unroll
            for (int j = 0; j < 4; j++)
                b2[j] = *(const unsigned long long*)(&Bs[k][tx * 8 + j * 2]);
            #pragma unroll
            for (int i = 0; i < 8; i++) {
                unsigned long long av;
                PACK_DUP(av, a[i]);
                #pragma unroll
                for (int j = 0; j < 4; j++)
                    FMA2(acc2[i][j], av, b2[j], acc2[i][j]);
            }
        }
        __syncthreads();
    }
    float bb[8];
    #pragma unroll
    for (int j = 0; j < 8; j++) bb[j] = bl[tx * 8 + j];
    #pragma unroll
    for (int i = 0; i < 8; i++) {
        int gr = m0 + ty * 8 + i;
        if (gr < N_NODES) {
            float o[8];
            #pragma unroll
            for (int j = 0; j < 4; j++)
                UNPACK2(o[2 * j], o[2 * j + 1], acc2[i][j]);
            float4 o0 = make_float4(o[0] + bb[0], o[1] + bb[1], o[2] + bb[2], o[3] + bb[3]);
            float4 o1 = make_float4(o[4] + bb[4], o[5] + bb[5], o[6] + bb[6], o[7] + bb[7]);
            *(float4*)(out + gr * 64 + tx * 8)     = o0;
            *(float4*)(out + gr * 64 + tx * 8 + 4) = o1;
        }
    }
}

// ---------------- launch ----------------
extern "C" void kernel_launch(void* const* d_in, const int* in_sizes, int n_in,
                              void* d_out, int out_size) {
    const float* x   = (const float*)d_in[0];
    const int*   y   = (const int*)d_in[1];
    const int*   ei  = (const int*)d_in[2];
    const float* emb = (const float*)d_in[3];
    const float* Wq = (const float*)d_in[4];  const float* bq = (const float*)d_in[5];
    const float* Wk = (const float*)d_in[6];  const float* bk = (const float*)d_in[7];
    const float* Wv = (const float*)d_in[8];  const float* bv = (const float*)d_in[9];
    const float* Ws = (const float*)d_in[10]; const float* bs = (const float*)d_in[11];
    const float* Wl = (const float*)d_in[12]; const float* bl = (const float*)d_in[13];
    float* out = (float*)d_out;

    k_xy  <<<(N_NODES * (F / 4) + 255) / 256, 256>>>(x, y, emb);
    k_zero<<<(N_NODES * HD / 4 + 255) / 256, 256>>>();
    k_proj<<<dim3((N_NODES + 127) / 128, 4), 256>>>(Wq, bq, Wk, bk, Wv, bv, Ws, bs);
    k_edge<<<(E_EDGES / 4 + 7) / 8, 256>>>(ei);   // 4 edges per warp
    k_cls <<<(N_NODES + 127) / 128, 128>>>(Wl, bl, out);
}